// round 1
// baseline (speedup 1.0000x reference)
#include <cuda_runtime.h>
#include <math.h>

#define NN   16384
#define DD   16
#define FIN  512
#define FOUT 512
#define RR   8
#define HIDD 64
#define BN_EPS 1e-5f
#define RESIDUAL 0.12f

// ---------------- scratch (device globals: allocation-free) ----------------
__device__ float g_att [(size_t)NN * RR * FIN];    // 268 MB, reused per pass
__device__ float g_srcz[(size_t)NN * RR * FOUT];   // 268 MB, reused per pass
__device__ float g_hz  [(size_t)NN * FOUT];        // 33 MB
__device__ float g_msg [2ull * NN * FOUT];         // 67 MB  (msg, msg_img)

__device__ __forceinline__ float lrelu(float x) { return x >= 0.0f ? x : 0.2f * x; }

// ---------------- kernel 1: relation maxpool ----------------
// att[n,r,f] = max over d of (rel[n,d]==r ? src[n,d,f] : 0), with the subtlety
// that if ALL d match r, no zero participates in the max.
__global__ void maxpool_kernel(const float* __restrict__ src,
                               const int*   __restrict__ rel,
                               float*       __restrict__ att)
{
    int n   = blockIdx.x;
    int tid = threadIdx.x;  // 128 threads; FIN/4 = 128 float4 lanes

    __shared__ int rl[DD];
    __shared__ int cnt[RR];
    if (tid < RR) cnt[tid] = 0;
    __syncthreads();
    if (tid < DD) {
        int r = rel[n * DD + tid];
        rl[tid] = r;
        atomicAdd(&cnt[r], 1);
    }
    __syncthreads();

    const float4* sp = reinterpret_cast<const float4*>(src + (size_t)n * DD * FIN);
    const float NEG = -3.402823466e38f;

    float4 mx[RR];
#pragma unroll
    for (int r = 0; r < RR; r++) mx[r] = make_float4(NEG, NEG, NEG, NEG);

#pragma unroll
    for (int d = 0; d < DD; d++) {
        float4 v = sp[d * (FIN / 4) + tid];
        int rd = rl[d];
#pragma unroll
        for (int r = 0; r < RR; r++) {
            bool m = (rd == r);
            mx[r].x = m ? fmaxf(mx[r].x, v.x) : mx[r].x;
            mx[r].y = m ? fmaxf(mx[r].y, v.y) : mx[r].y;
            mx[r].z = m ? fmaxf(mx[r].z, v.z) : mx[r].z;
            mx[r].w = m ? fmaxf(mx[r].w, v.w) : mx[r].w;
        }
    }

    float4* ap = reinterpret_cast<float4*>(att + (size_t)n * RR * FIN);
#pragma unroll
    for (int r = 0; r < RR; r++) {
        float4 o = mx[r];
        if (cnt[r] != DD) {  // at least one masked zero participates in the max
            o.x = fmaxf(o.x, 0.0f);
            o.y = fmaxf(o.y, 0.0f);
            o.z = fmaxf(o.z, 0.0f);
            o.w = fmaxf(o.w, 0.0f);
        }
        ap[r * (FIN / 4) + tid] = o;
    }
}

// ---------------- kernel 2: tiled fp32 GEMM, C = lrelu(A @ B) ----------------
// A: [M, 512] row-major, B: [512, 512] row-major, C: [M, 512].
// BM=128, BN=64, BK=16, 256 threads, 8x4 per-thread microtile.
__global__ void gemm_lrelu_kernel(const float* __restrict__ A,
                                  const float* __restrict__ B,
                                  float*       __restrict__ C,
                                  int M)
{
    constexpr int BM = 128, BN = 64, BK = 16;
    constexpr int K = FIN, NC = FOUT;

    __shared__ float As[BK][BM + 4];  // transposed A tile, padded
    __shared__ float Bs[BK][BN];

    int tid = threadIdx.x;            // 256
    int tx = tid & 15;                // 0..15 -> 64 cols (4 each)
    int ty = tid >> 4;                // 0..15 -> 128 rows (8 each)
    int bm = blockIdx.y * BM;
    int bn = blockIdx.x * BN;

    float acc[8][4];
#pragma unroll
    for (int i = 0; i < 8; i++)
#pragma unroll
        for (int j = 0; j < 4; j++) acc[i][j] = 0.0f;

    for (int k0 = 0; k0 < K; k0 += BK) {
        // load A tile: 128x16 floats = 512 float4, 2 per thread
#pragma unroll
        for (int t = 0; t < 2; t++) {
            int idx = tid * 2 + t;           // 0..511
            int row = idx >> 2;              // 0..127
            int kc  = (idx & 3) * 4;         // 0,4,8,12
            float4 v = *reinterpret_cast<const float4*>(
                A + (size_t)(bm + row) * K + k0 + kc);
            As[kc + 0][row] = v.x;
            As[kc + 1][row] = v.y;
            As[kc + 2][row] = v.z;
            As[kc + 3][row] = v.w;
        }
        // load B tile: 16x64 floats = 256 float4, 1 per thread
        {
            int row = tid >> 4;              // 0..15
            int col = (tid & 15) * 4;        // 0..60
            float4 v = *reinterpret_cast<const float4*>(
                B + (size_t)(k0 + row) * NC + bn + col);
            *reinterpret_cast<float4*>(&Bs[row][col]) = v;
        }
        __syncthreads();

#pragma unroll
        for (int kk = 0; kk < BK; kk++) {
            const float4* Ar = reinterpret_cast<const float4*>(&As[kk][ty * 8]);
            float4 a0 = Ar[0];
            float4 a1 = Ar[1];
            float4 bv = *reinterpret_cast<const float4*>(&Bs[kk][tx * 4]);
            float a[8] = {a0.x, a0.y, a0.z, a0.w, a1.x, a1.y, a1.z, a1.w};
            float b[4] = {bv.x, bv.y, bv.z, bv.w};
#pragma unroll
            for (int i = 0; i < 8; i++)
#pragma unroll
                for (int j = 0; j < 4; j++) acc[i][j] += a[i] * b[j];
        }
        __syncthreads();
    }

#pragma unroll
    for (int i = 0; i < 8; i++) {
        int m = bm + ty * 8 + i;
        float4 o;
        o.x = lrelu(acc[i][0]);
        o.y = lrelu(acc[i][1]);
        o.z = lrelu(acc[i][2]);
        o.w = lrelu(acc[i][3]);
        *reinterpret_cast<float4*>(C + (size_t)m * NC + bn + tx * 4) = o;
    }
}

// ---------------- kernel 3: GAT softmax epilogue ----------------
// one block per node, 256 threads. scores[r] = lrelu(dot(src_z[n,r], a[:512]) + dot(h_z[n], a[512:]))
// alpha = softmax_r; msg = sum_r alpha*src_z + 0.12*h_z
__global__ void gat_epilogue_kernel(const float* __restrict__ srcz,
                                    const float* __restrict__ hz,
                                    const float* __restrict__ a_attn,
                                    float*       __restrict__ msg)
{
    int n   = blockIdx.x;
    int tid = threadIdx.x;  // 256

    __shared__ float zs[RR][FOUT];
    __shared__ float hzs[FOUT];
    __shared__ float red[72];
    __shared__ float scoresm[9];
    __shared__ float alpha[RR];

    const float* zp = srcz + (size_t)n * RR * FOUT;
    for (int idx = tid; idx < RR * FOUT; idx += 256)
        zs[idx >> 9][idx & (FOUT - 1)] = zp[idx];
    for (int f = tid; f < FOUT; f += 256)
        hzs[f] = hz[(size_t)n * FOUT + f];
    __syncthreads();

    float p[9];
#pragma unroll
    for (int r = 0; r < 9; r++) p[r] = 0.0f;

    for (int f = tid; f < FOUT; f += 256) {
        float af = a_attn[f];
#pragma unroll
        for (int r = 0; r < RR; r++) p[r] += zs[r][f] * af;
        p[8] += hzs[f] * a_attn[FOUT + f];
    }

    int lane = tid & 31, warp = tid >> 5;
#pragma unroll
    for (int r = 0; r < 9; r++) {
        float v = p[r];
#pragma unroll
        for (int off = 16; off; off >>= 1)
            v += __shfl_down_sync(0xffffffffu, v, off);
        if (lane == 0) red[r * 8 + warp] = v;
    }
    __syncthreads();
    if (tid < 9) {
        float s = 0.0f;
#pragma unroll
        for (int w = 0; w < 8; w++) s += red[tid * 8 + w];
        scoresm[tid] = s;
    }
    __syncthreads();
    if (tid == 0) {
        float sh = scoresm[8];
        float sc[RR], mx = -3.402823466e38f;
#pragma unroll
        for (int r = 0; r < RR; r++) {
            sc[r] = lrelu(scoresm[r] + sh);
            mx = fmaxf(mx, sc[r]);
        }
        float sum = 0.0f;
#pragma unroll
        for (int r = 0; r < RR; r++) {
            float e = expf(sc[r] - mx);
            alpha[r] = e;
            sum += e;
        }
        float inv = 1.0f / sum;
#pragma unroll
        for (int r = 0; r < RR; r++) alpha[r] *= inv;
    }
    __syncthreads();

    float al[RR];
#pragma unroll
    for (int r = 0; r < RR; r++) al[r] = alpha[r];

    for (int f = tid; f < FOUT; f += 256) {
        float acc = RESIDUAL * hzs[f];
#pragma unroll
        for (int r = 0; r < RR; r++) acc += al[r] * zs[r][f];
        msg[(size_t)n * FOUT + f] = acc;
    }
}

// ---------------- kernel 4: multi-attention + BatchNorm ----------------
// one block per node, 128 threads.
__global__ void final_kernel(const float* __restrict__ Wp1,
                             const float* __restrict__ bp1,
                             const float* __restrict__ Wp2,
                             const float* __restrict__ bp2,
                             const float* __restrict__ gamma,
                             const float* __restrict__ betaBN,
                             const float* __restrict__ mean,
                             const float* __restrict__ var,
                             float*       __restrict__ out)
{
    int n   = blockIdx.x;
    int tid = threadIdx.x;  // 128

    __shared__ float z[2][FOUT];
    __shared__ float wred[4];
    __shared__ float betasm[2];

    for (int f = tid; f < FOUT; f += 128) {
        z[0][f] = g_msg[(size_t)n * FOUT + f];
        z[1][f] = g_msg[(size_t)NN * FOUT + (size_t)n * FOUT + f];
    }
    __syncthreads();

    // z @ W_p1 + b_p1 -> tanh -> (·W_p2) partials. thread t: i=t/64, hid=t%64
    int i  = tid >> 6;
    int hd = tid & 63;
    float acc = 0.0f;
#pragma unroll 8
    for (int k = 0; k < FOUT; k++) acc += z[i][k] * Wp1[k * HIDD + hd];
    float t  = tanhf(acc + bp1[hd]);
    float pw = t * Wp2[hd];

#pragma unroll
    for (int off = 16; off; off >>= 1)
        pw += __shfl_down_sync(0xffffffffu, pw, off);
    if ((tid & 31) == 0) wred[tid >> 5] = pw;
    __syncthreads();
    if (tid == 0) {
        float w0 = tanhf(wred[0] + wred[1] + bp2[0]);
        float w1 = tanhf(wred[2] + wred[3] + bp2[0]);
        float m  = fmaxf(w0, w1);
        float e0 = expf(w0 - m), e1 = expf(w1 - m);
        float inv = 1.0f / (e0 + e1);
        betasm[0] = e0 * inv;
        betasm[1] = e1 * inv;
    }
    __syncthreads();

    float b0 = betasm[0], b1 = betasm[1];
    for (int f = tid; f < FOUT; f += 128) {
        float v = b0 * z[0][f] + b1 * z[1][f];
        out[(size_t)n * FOUT + f] =
            (v - mean[f]) * rsqrtf(var[f] + BN_EPS) * gamma[f] + betaBN[f];
    }
}

// ---------------- launch ----------------
extern "C" void kernel_launch(void* const* d_in, const int* in_sizes, int n_in,
                              void* d_out, int out_size)
{
    const float* src_h     = (const float*)d_in[0];
    const float* src_h_img = (const float*)d_in[1];
    const int*   rel       = (const int*)  d_in[2];
    const float* h         = (const float*)d_in[3];
    const float* h_img     = (const float*)d_in[4];
    const float* W0        = (const float*)d_in[5];
    const float* a0        = (const float*)d_in[6];
    const float* W1        = (const float*)d_in[7];
    const float* a1        = (const float*)d_in[8];
    const float* Wp1       = (const float*)d_in[9];
    const float* bp1       = (const float*)d_in[10];
    const float* Wp2       = (const float*)d_in[11];
    const float* bp2       = (const float*)d_in[12];
    const float* gamma     = (const float*)d_in[13];
    const float* betaBN    = (const float*)d_in[14];
    const float* mean      = (const float*)d_in[15];
    const float* var       = (const float*)d_in[16];
    float* out = (float*)d_out;

    float *att, *srcz, *hz, *msg;
    cudaGetSymbolAddress((void**)&att,  g_att);
    cudaGetSymbolAddress((void**)&srcz, g_srcz);
    cudaGetSymbolAddress((void**)&hz,   g_hz);
    cudaGetSymbolAddress((void**)&msg,  g_msg);

    const float* srcs[2] = {src_h, src_h_img};
    const float* hs[2]   = {h, h_img};
    const float* Ws[2]   = {W0, W1};
    const float* as[2]   = {a0, a1};

    dim3 gemm_big_grid(FOUT / 64, (NN * RR) / 128);
    dim3 gemm_hz_grid (FOUT / 64, NN / 128);

    for (int pass = 0; pass < 2; pass++) {
        maxpool_kernel<<<NN, 128>>>(srcs[pass], rel, att);
        gemm_lrelu_kernel<<<gemm_big_grid, 256>>>(att, Ws[pass], srcz, NN * RR);
        gemm_lrelu_kernel<<<gemm_hz_grid, 256>>>(hs[pass], Ws[pass], hz, NN);
        gat_epilogue_kernel<<<NN, 256>>>(srcz, hz, as[pass],
                                         msg + (size_t)pass * NN * FOUT);
    }
    final_kernel<<<NN, 128>>>(Wp1, bp1, Wp2, bp2, gamma, betaBN, mean, var, out);
}

// round 3
// speedup vs baseline: 2.1629x; 2.1629x over previous
#include <cuda_runtime.h>
#include <math.h>
#include <cstdint>

#define NN   16384
#define DD   16
#define FIN  512
#define FOUT 512
#define RR   8
#define HIDD 64
#define BN_EPS 1e-5f
#define RESIDUAL 0.12f

// ---------------- scratch (device globals: allocation-free) ----------------
__device__ float g_att  [(size_t)NN * RR * FIN];    // 268 MB (tf32-rounded)
__device__ float g_srcz [(size_t)NN * RR * FOUT];   // 268 MB
__device__ float g_hz   [(size_t)NN * FOUT];        // 33 MB
__device__ float g_msg  [2ull * NN * FOUT];         // 67 MB
__device__ float g_wt   [(size_t)FIN * FOUT];       // 1 MB (W^T, tf32-rounded)
__device__ float g_hconv[(size_t)NN * FIN];         // 33 MB (h, tf32-rounded)

__device__ __forceinline__ float lrelu(float x) { return x >= 0.0f ? x : 0.2f * x; }

__device__ __forceinline__ float to_tf32(float x) {
    float r;
    asm("cvt.rn.tf32.f32 %0, %1;" : "=f"(r) : "f"(x));
    return r;
}

__device__ __forceinline__ uint32_t smem_u32(const void* p) {
    uint32_t a;
    asm("{ .reg .u64 t; cvta.to.shared.u64 t, %1; cvt.u32.u64 %0, t; }" : "=r"(a) : "l"(p));
    return a;
}
__device__ __forceinline__ void cp_async16(uint32_t dst, const void* src) {
    asm volatile("cp.async.cg.shared.global [%0], [%1], 16;" :: "r"(dst), "l"(src));
}
#define CP_COMMIT() asm volatile("cp.async.commit_group;" ::: "memory")
#define CP_WAIT(n)  asm volatile("cp.async.wait_group %0;" :: "n"(n) : "memory")

__device__ __forceinline__ void mma_tf32(float& c0, float& c1, float& c2, float& c3,
                                         uint32_t a0, uint32_t a1, uint32_t a2, uint32_t a3,
                                         uint32_t b0, uint32_t b1) {
    asm volatile(
        "mma.sync.aligned.m16n8k8.row.col.f32.tf32.tf32.f32 "
        "{%0,%1,%2,%3}, {%4,%5,%6,%7}, {%8,%9}, {%0,%1,%2,%3};"
        : "+f"(c0), "+f"(c1), "+f"(c2), "+f"(c3)
        : "r"(a0), "r"(a1), "r"(a2), "r"(a3), "r"(b0), "r"(b1));
}

// ---------------- kernel 0a: transpose W [K,N] -> WT [N,K], tf32 round ----------------
__global__ void transposeW_kernel(const float* __restrict__ W, float* __restrict__ WT)
{
    __shared__ float t[32][33];
    int bx = blockIdx.x * 32, by = blockIdx.y * 32;
    t[threadIdx.y][threadIdx.x] = W[(by + threadIdx.y) * FOUT + bx + threadIdx.x];
    __syncthreads();
    WT[(bx + threadIdx.y) * FIN + by + threadIdx.x] = to_tf32(t[threadIdx.x][threadIdx.y]);
}

// ---------------- kernel 0b: round h to tf32 ----------------
__global__ void convert_kernel(const float* __restrict__ in, float* __restrict__ out, int n4)
{
    int i = blockIdx.x * blockDim.x + threadIdx.x;
    if (i < n4) {
        float4 v = reinterpret_cast<const float4*>(in)[i];
        v.x = to_tf32(v.x); v.y = to_tf32(v.y);
        v.z = to_tf32(v.z); v.w = to_tf32(v.w);
        reinterpret_cast<float4*>(out)[i] = v;
    }
}

// ---------------- kernel 1: relation maxpool (tf32-rounded output) ----------------
__global__ void maxpool_kernel(const float* __restrict__ src,
                               const int*   __restrict__ rel,
                               float*       __restrict__ att)
{
    int n   = blockIdx.x;
    int tid = threadIdx.x;  // 128

    __shared__ int rl[DD];
    __shared__ int cnt[RR];
    if (tid < RR) cnt[tid] = 0;
    __syncthreads();
    if (tid < DD) {
        int r = rel[n * DD + tid];
        rl[tid] = r;
        atomicAdd(&cnt[r], 1);
    }
    __syncthreads();

    const float4* sp = reinterpret_cast<const float4*>(src + (size_t)n * DD * FIN);
    const float NEG = -3.402823466e38f;

    float4 mx[RR];
#pragma unroll
    for (int r = 0; r < RR; r++) mx[r] = make_float4(NEG, NEG, NEG, NEG);

#pragma unroll
    for (int d = 0; d < DD; d++) {
        float4 v = sp[d * (FIN / 4) + tid];
        int rd = rl[d];
#pragma unroll
        for (int r = 0; r < RR; r++) {
            bool m = (rd == r);
            mx[r].x = m ? fmaxf(mx[r].x, v.x) : mx[r].x;
            mx[r].y = m ? fmaxf(mx[r].y, v.y) : mx[r].y;
            mx[r].z = m ? fmaxf(mx[r].z, v.z) : mx[r].z;
            mx[r].w = m ? fmaxf(mx[r].w, v.w) : mx[r].w;
        }
    }

    float4* ap = reinterpret_cast<float4*>(att + (size_t)n * RR * FIN);
#pragma unroll
    for (int r = 0; r < RR; r++) {
        float4 o = mx[r];
        if (cnt[r] != DD) {
            o.x = fmaxf(o.x, 0.0f);
            o.y = fmaxf(o.y, 0.0f);
            o.z = fmaxf(o.z, 0.0f);
            o.w = fmaxf(o.w, 0.0f);
        }
        o.x = to_tf32(o.x); o.y = to_tf32(o.y);
        o.z = to_tf32(o.z); o.w = to_tf32(o.w);
        ap[r * (FIN / 4) + tid] = o;
    }
}

// ---------------- kernel 2: mma.sync tf32 GEMM, C = lrelu(A @ WT^T) ----------------
// A: [M, 512] row-major (tf32-rounded). Bt: [512(N), 512(K)] row-major (tf32-rounded).
// BM=128, BN=128, BK=16. 256 threads, 8 warps (2M x 4N), warp tile 64x32.
#define TSTRIDE 20   // smem row stride (floats): conflict-free fragment loads

__shared__ float sh_A[2][128][TSTRIDE];
__shared__ float sh_B[2][128][TSTRIDE];

__global__ void __launch_bounds__(256, 2)
gemm_tc_kernel(const float* __restrict__ A,
               const float* __restrict__ Bt,
               float*       __restrict__ C)
{
    int tid  = threadIdx.x;
    int wid  = tid >> 5;
    int lane = tid & 31;
    int wm   = wid & 1;         // 0..1 -> 64-row slab
    int wn   = wid >> 1;        // 0..3 -> 32-col slab
    int g    = lane >> 2;       // 0..7
    int t    = lane & 3;        // 0..3

    int bm = blockIdx.y * 128;
    int bn = blockIdx.x * 128;

    // cp.async source/dest indexing: thread copies (tid) and (tid+256) of 512 float4s
    int row0 = tid >> 2;              // 0..63
    int kc0  = (tid & 3) * 4;         // 0,4,8,12
    const float* Ag0 = A  + (size_t)(bm + row0)      * FIN + kc0;
    const float* Ag1 = A  + (size_t)(bm + row0 + 64) * FIN + kc0;
    const float* Bg0 = Bt + (size_t)(bn + row0)      * FIN + kc0;
    const float* Bg1 = Bt + (size_t)(bn + row0 + 64) * FIN + kc0;

    uint32_t sA0[2], sA1[2], sB0[2], sB1[2];
#pragma unroll
    for (int b = 0; b < 2; b++) {
        sA0[b] = smem_u32(&sh_A[b][row0][kc0]);
        sA1[b] = smem_u32(&sh_A[b][row0 + 64][kc0]);
        sB0[b] = smem_u32(&sh_B[b][row0][kc0]);
        sB1[b] = smem_u32(&sh_B[b][row0 + 64][kc0]);
    }

    float acc[4][4][4];
#pragma unroll
    for (int i = 0; i < 4; i++)
#pragma unroll
        for (int j = 0; j < 4; j++)
#pragma unroll
            for (int q = 0; q < 4; q++) acc[i][j][q] = 0.0f;

    const int NK = FIN / 16;  // 32 stages

    // prologue: stages 0 and 1
#pragma unroll
    for (int s = 0; s < 2; s++) {
        int k0 = s * 16;
        cp_async16(sA0[s], Ag0 + k0);
        cp_async16(sA1[s], Ag1 + k0);
        cp_async16(sB0[s], Bg0 + k0);
        cp_async16(sB1[s], Bg1 + k0);
        CP_COMMIT();
    }
    CP_WAIT(1);
    __syncthreads();

    for (int i = 0; i < NK; i++) {
        int buf = i & 1;
        // ---- compute stage i ----
        const float (*As)[TSTRIDE] = sh_A[buf];
        const float (*Bs)[TSTRIDE] = sh_B[buf];
#pragma unroll
        for (int kk = 0; kk < 2; kk++) {
            int k = kk * 8;
            uint32_t a[4][4];
#pragma unroll
            for (int mt = 0; mt < 4; mt++) {
                int mrow = wm * 64 + mt * 16 + g;
                a[mt][0] = __float_as_uint(As[mrow    ][k + t    ]);
                a[mt][1] = __float_as_uint(As[mrow + 8][k + t    ]);
                a[mt][2] = __float_as_uint(As[mrow    ][k + t + 4]);
                a[mt][3] = __float_as_uint(As[mrow + 8][k + t + 4]);
            }
            uint32_t b[4][2];
#pragma unroll
            for (int nt = 0; nt < 4; nt++) {
                int nrow = wn * 32 + nt * 8 + g;
                b[nt][0] = __float_as_uint(Bs[nrow][k + t    ]);
                b[nt][1] = __float_as_uint(Bs[nrow][k + t + 4]);
            }
#pragma unroll
            for (int mt = 0; mt < 4; mt++)
#pragma unroll
                for (int nt = 0; nt < 4; nt++)
                    mma_tf32(acc[mt][nt][0], acc[mt][nt][1], acc[mt][nt][2], acc[mt][nt][3],
                             a[mt][0], a[mt][1], a[mt][2], a[mt][3],
                             b[nt][0], b[nt][1]);
        }
        __syncthreads();
        // ---- prefetch stage i+2 into the buffer just freed ----
        if (i + 2 < NK) {
            int k0 = (i + 2) * 16;
            cp_async16(sA0[buf], Ag0 + k0);
            cp_async16(sA1[buf], Ag1 + k0);
            cp_async16(sB0[buf], Bg0 + k0);
            cp_async16(sB1[buf], Bg1 + k0);
            CP_COMMIT();
        }
        if (i + 1 < NK) {
            if (i + 2 < NK) { CP_WAIT(1); } else { CP_WAIT(0); }
            __syncthreads();
        }
    }

    // ---- epilogue: lrelu + store ----
#pragma unroll
    for (int mt = 0; mt < 4; mt++) {
        int mrow = bm + wm * 64 + mt * 16 + g;
#pragma unroll
        for (int nt = 0; nt < 4; nt++) {
            int ncol = bn + wn * 32 + nt * 8 + t * 2;
            float2 lo, hi;
            lo.x = lrelu(acc[mt][nt][0]);
            lo.y = lrelu(acc[mt][nt][1]);
            hi.x = lrelu(acc[mt][nt][2]);
            hi.y = lrelu(acc[mt][nt][3]);
            *reinterpret_cast<float2*>(C + (size_t)mrow * FOUT + ncol)       = lo;
            *reinterpret_cast<float2*>(C + (size_t)(mrow + 8) * FOUT + ncol) = hi;
        }
    }
}

// ---------------- kernel 3: GAT softmax epilogue ----------------
__global__ void gat_epilogue_kernel(const float* __restrict__ srcz,
                                    const float* __restrict__ hz,
                                    const float* __restrict__ a_attn,
                                    float*       __restrict__ msg)
{
    int n   = blockIdx.x;
    int tid = threadIdx.x;  // 256

    __shared__ float zs[RR][FOUT];
    __shared__ float hzs[FOUT];
    __shared__ float red[72];
    __shared__ float scoresm[9];
    __shared__ float alpha[RR];

    const float* zp = srcz + (size_t)n * RR * FOUT;
    for (int idx = tid; idx < RR * FOUT; idx += 256)
        zs[idx >> 9][idx & (FOUT - 1)] = zp[idx];
    for (int f = tid; f < FOUT; f += 256)
        hzs[f] = hz[(size_t)n * FOUT + f];
    __syncthreads();

    float p[9];
#pragma unroll
    for (int r = 0; r < 9; r++) p[r] = 0.0f;

    for (int f = tid; f < FOUT; f += 256) {
        float af = a_attn[f];
#pragma unroll
        for (int r = 0; r < RR; r++) p[r] += zs[r][f] * af;
        p[8] += hzs[f] * a_attn[FOUT + f];
    }

    int lane = tid & 31, warp = tid >> 5;
#pragma unroll
    for (int r = 0; r < 9; r++) {
        float v = p[r];
#pragma unroll
        for (int off = 16; off; off >>= 1)
            v += __shfl_down_sync(0xffffffffu, v, off);
        if (lane == 0) red[r * 8 + warp] = v;
    }
    __syncthreads();
    if (tid < 9) {
        float s = 0.0f;
#pragma unroll
        for (int w = 0; w < 8; w++) s += red[tid * 8 + w];
        scoresm[tid] = s;
    }
    __syncthreads();
    if (tid == 0) {
        float sh = scoresm[8];
        float sc[RR], mx = -3.402823466e38f;
#pragma unroll
        for (int r = 0; r < RR; r++) {
            sc[r] = lrelu(scoresm[r] + sh);
            mx = fmaxf(mx, sc[r]);
        }
        float sum = 0.0f;
#pragma unroll
        for (int r = 0; r < RR; r++) {
            float e = expf(sc[r] - mx);
            alpha[r] = e;
            sum += e;
        }
        float inv = 1.0f / sum;
#pragma unroll
        for (int r = 0; r < RR; r++) alpha[r] *= inv;
    }
    __syncthreads();

    float al[RR];
#pragma unroll
    for (int r = 0; r < RR; r++) al[r] = alpha[r];

    for (int f = tid; f < FOUT; f += 256) {
        float acc = RESIDUAL * hzs[f];
#pragma unroll
        for (int r = 0; r < RR; r++) acc += al[r] * zs[r][f];
        msg[(size_t)n * FOUT + f] = acc;
    }
}

// ---------------- kernel 4: multi-attention + BatchNorm ----------------
__global__ void final_kernel(const float* __restrict__ Wp1,
                             const float* __restrict__ bp1,
                             const float* __restrict__ Wp2,
                             const float* __restrict__ bp2,
                             const float* __restrict__ gamma,
                             const float* __restrict__ betaBN,
                             const float* __restrict__ mean,
                             const float* __restrict__ var,
                             float*       __restrict__ out)
{
    int n   = blockIdx.x;
    int tid = threadIdx.x;  // 128

    __shared__ float z[2][FOUT];
    __shared__ float wred[4];
    __shared__ float betasm[2];

    for (int f = tid; f < FOUT; f += 128) {
        z[0][f] = g_msg[(size_t)n * FOUT + f];
        z[1][f] = g_msg[(size_t)NN * FOUT + (size_t)n * FOUT + f];
    }
    __syncthreads();

    int i  = tid >> 6;
    int hd = tid & 63;
    float acc = 0.0f;
#pragma unroll 8
    for (int k = 0; k < FOUT; k++) acc += z[i][k] * Wp1[k * HIDD + hd];
    float t  = tanhf(acc + bp1[hd]);
    float pw = t * Wp2[hd];

#pragma unroll
    for (int off = 16; off; off >>= 1)
        pw += __shfl_down_sync(0xffffffffu, pw, off);
    if ((tid & 31) == 0) wred[tid >> 5] = pw;
    __syncthreads();
    if (tid == 0) {
        float w0 = tanhf(wred[0] + wred[1] + bp2[0]);
        float w1 = tanhf(wred[2] + wred[3] + bp2[0]);
        float m  = fmaxf(w0, w1);
        float e0 = expf(w0 - m), e1 = expf(w1 - m);
        float inv = 1.0f / (e0 + e1);
        betasm[0] = e0 * inv;
        betasm[1] = e1 * inv;
    }
    __syncthreads();

    float b0 = betasm[0], b1 = betasm[1];
    for (int f = tid; f < FOUT; f += 128) {
        float v = b0 * z[0][f] + b1 * z[1][f];
        out[(size_t)n * FOUT + f] =
            (v - mean[f]) * rsqrtf(var[f] + BN_EPS) * gamma[f] + betaBN[f];
    }
}

// ---------------- launch ----------------
extern "C" void kernel_launch(void* const* d_in, const int* in_sizes, int n_in,
                              void* d_out, int out_size)
{
    const float* src_h     = (const float*)d_in[0];
    const float* src_h_img = (const float*)d_in[1];
    const int*   rel       = (const int*)  d_in[2];
    const float* h         = (const float*)d_in[3];
    const float* h_img     = (const float*)d_in[4];
    const float* W0        = (const float*)d_in[5];
    const float* a0        = (const float*)d_in[6];
    const float* W1        = (const float*)d_in[7];
    const float* a1        = (const float*)d_in[8];
    const float* Wp1       = (const float*)d_in[9];
    const float* bp1       = (const float*)d_in[10];
    const float* Wp2       = (const float*)d_in[11];
    const float* bp2       = (const float*)d_in[12];
    const float* gamma     = (const float*)d_in[13];
    const float* betaBN    = (const float*)d_in[14];
    const float* mean      = (const float*)d_in[15];
    const float* var       = (const float*)d_in[16];
    float* out = (float*)d_out;

    float *att, *srcz, *hz, *msg, *wt, *hconv;
    cudaGetSymbolAddress((void**)&att,   g_att);
    cudaGetSymbolAddress((void**)&srcz,  g_srcz);
    cudaGetSymbolAddress((void**)&hz,    g_hz);
    cudaGetSymbolAddress((void**)&msg,   g_msg);
    cudaGetSymbolAddress((void**)&wt,    g_wt);
    cudaGetSymbolAddress((void**)&hconv, g_hconv);

    const float* srcs[2] = {src_h, src_h_img};
    const float* hs[2]   = {h, h_img};
    const float* Ws[2]   = {W0, W1};
    const float* as[2]   = {a0, a1};

    for (int pass = 0; pass < 2; pass++) {
        transposeW_kernel<<<dim3(16, 16), dim3(32, 32)>>>(Ws[pass], wt);
        convert_kernel<<<(NN * FIN / 4 + 255) / 256, 256>>>(hs[pass], hconv, NN * FIN / 4);
        maxpool_kernel<<<NN, 128>>>(srcs[pass], rel, att);
        gemm_tc_kernel<<<dim3(FOUT / 128, (NN * RR) / 128), 256>>>(att, wt, srcz);
        gemm_tc_kernel<<<dim3(FOUT / 128, NN / 128), 256>>>(hconv, wt, hz);
        gat_epilogue_kernel<<<NN, 256>>>(srcz, hz, as[pass],
                                         msg + (size_t)pass * NN * FOUT);
    }
    final_kernel<<<NN, 128>>>(Wp1, bp1, Wp2, bp2, gamma, betaBN, mean, var, out);
}

// round 4
// speedup vs baseline: 2.5383x; 1.1736x over previous
#include <cuda_runtime.h>
#include <math.h>
#include <cstdint>

#define NN   16384
#define DD   16
#define FIN  512
#define FOUT 512
#define RR   8
#define HIDD 64
#define BN_EPS 1e-5f
#define RESIDUAL 0.12f

// ---------------- scratch (device globals: allocation-free) ----------------
__device__ float g_att  [(size_t)NN * RR * FIN];    // 268 MB (tf32-rounded)
__device__ float g_srcz [(size_t)NN * RR * FOUT];   // 268 MB
__device__ float g_hz   [(size_t)NN * FOUT];        // 33 MB
__device__ float g_msg  [2ull * NN * FOUT];         // 67 MB
__device__ float g_wt   [(size_t)FIN * FOUT];       // 1 MB (W^T, tf32-rounded)
__device__ float g_hconv[(size_t)NN * FIN];         // 33 MB (h, tf32-rounded)

__device__ __forceinline__ float lrelu(float x) { return x >= 0.0f ? x : 0.2f * x; }

__device__ __forceinline__ float to_tf32(float x) {
    float r;
    asm("cvt.rn.tf32.f32 %0, %1;" : "=f"(r) : "f"(x));
    return r;
}

__device__ __forceinline__ uint32_t smem_u32(const void* p) {
    uint32_t a;
    asm("{ .reg .u64 t; cvta.to.shared.u64 t, %1; cvt.u32.u64 %0, t; }" : "=r"(a) : "l"(p));
    return a;
}
__device__ __forceinline__ void cp_async16(uint32_t dst, const void* src) {
    asm volatile("cp.async.cg.shared.global [%0], [%1], 16;" :: "r"(dst), "l"(src));
}
#define CP_COMMIT() asm volatile("cp.async.commit_group;" ::: "memory")
#define CP_WAIT(n)  asm volatile("cp.async.wait_group %0;" :: "n"(n) : "memory")

__device__ __forceinline__ void mma_tf32(float& c0, float& c1, float& c2, float& c3,
                                         uint32_t a0, uint32_t a1, uint32_t a2, uint32_t a3,
                                         uint32_t b0, uint32_t b1) {
    asm volatile(
        "mma.sync.aligned.m16n8k8.row.col.f32.tf32.tf32.f32 "
        "{%0,%1,%2,%3}, {%4,%5,%6,%7}, {%8,%9}, {%0,%1,%2,%3};"
        : "+f"(c0), "+f"(c1), "+f"(c2), "+f"(c3)
        : "r"(a0), "r"(a1), "r"(a2), "r"(a3), "r"(b0), "r"(b1));
}

// ---------------- kernel 0a: transpose W [K,N] -> WT [N,K], tf32 round ----------------
__global__ void transposeW_kernel(const float* __restrict__ W, float* __restrict__ WT)
{
    __shared__ float t[32][33];
    int bx = blockIdx.x * 32, by = blockIdx.y * 32;
    t[threadIdx.y][threadIdx.x] = W[(by + threadIdx.y) * FOUT + bx + threadIdx.x];
    __syncthreads();
    WT[(bx + threadIdx.y) * FIN + by + threadIdx.x] = to_tf32(t[threadIdx.x][threadIdx.y]);
}

// ---------------- kernel 0b: round h to tf32 ----------------
__global__ void convert_kernel(const float* __restrict__ in, float* __restrict__ out, int n4)
{
    int i = blockIdx.x * blockDim.x + threadIdx.x;
    if (i < n4) {
        float4 v = reinterpret_cast<const float4*>(in)[i];
        v.x = to_tf32(v.x); v.y = to_tf32(v.y);
        v.z = to_tf32(v.z); v.w = to_tf32(v.w);
        reinterpret_cast<float4*>(out)[i] = v;
    }
}

// ---------------- kernel 1: relation maxpool (tf32-rounded output) ----------------
__global__ void maxpool_kernel(const float* __restrict__ src,
                               const int*   __restrict__ rel,
                               float*       __restrict__ att)
{
    int n   = blockIdx.x;
    int tid = threadIdx.x;  // 128

    __shared__ int rl[DD];
    __shared__ int cnt[RR];
    if (tid < RR) cnt[tid] = 0;
    __syncthreads();
    if (tid < DD) {
        int r = rel[n * DD + tid];
        rl[tid] = r;
        atomicAdd(&cnt[r], 1);
    }
    __syncthreads();

    const float4* sp = reinterpret_cast<const float4*>(src + (size_t)n * DD * FIN);
    const float NEG = -3.402823466e38f;

    float4 mx[RR];
#pragma unroll
    for (int r = 0; r < RR; r++) mx[r] = make_float4(NEG, NEG, NEG, NEG);

#pragma unroll
    for (int d = 0; d < DD; d++) {
        float4 v = sp[d * (FIN / 4) + tid];
        int rd = rl[d];
#pragma unroll
        for (int r = 0; r < RR; r++) {
            bool m = (rd == r);
            mx[r].x = m ? fmaxf(mx[r].x, v.x) : mx[r].x;
            mx[r].y = m ? fmaxf(mx[r].y, v.y) : mx[r].y;
            mx[r].z = m ? fmaxf(mx[r].z, v.z) : mx[r].z;
            mx[r].w = m ? fmaxf(mx[r].w, v.w) : mx[r].w;
        }
    }

    float4* ap = reinterpret_cast<float4*>(att + (size_t)n * RR * FIN);
#pragma unroll
    for (int r = 0; r < RR; r++) {
        float4 o = mx[r];
        if (cnt[r] != DD) {
            o.x = fmaxf(o.x, 0.0f);
            o.y = fmaxf(o.y, 0.0f);
            o.z = fmaxf(o.z, 0.0f);
            o.w = fmaxf(o.w, 0.0f);
        }
        o.x = to_tf32(o.x); o.y = to_tf32(o.y);
        o.z = to_tf32(o.z); o.w = to_tf32(o.w);
        ap[r * (FIN / 4) + tid] = o;
    }
}

// ---------------- kernel 2: mma.sync tf32 GEMM, C = lrelu(A @ WT^T) ----------------
// 4-stage cp.async ring, one __syncthreads per BK=16 stage.
// BM=128, BN=128, BK=16. 256 threads, 8 warps (2M x 4N), warp tile 64x32.
#define TSTRIDE 20                        // smem row stride (floats)
#define STAGE_FLOATS (2 * 128 * TSTRIDE)  // A tile + B tile per stage
#define GSTAGES 4
#define GEMM_SMEM (GSTAGES * STAGE_FLOATS * 4)  // 81920 bytes

__global__ void __launch_bounds__(256, 2)
gemm_tc_kernel(const float* __restrict__ A,
               const float* __restrict__ Bt,
               float*       __restrict__ C)
{
    extern __shared__ float sm[];
    int tid  = threadIdx.x;
    int wid  = tid >> 5;
    int lane = tid & 31;
    int wm   = wid & 1;
    int wn   = wid >> 1;
    int g    = lane >> 2;
    int t    = lane & 3;

    int bm = blockIdx.y * 128;
    int bn = blockIdx.x * 128;

    int row0 = tid >> 2;              // 0..63
    int kc0  = (tid & 3) * 4;         // 0,4,8,12
    const float* Ag0 = A  + (size_t)(bm + row0)      * FIN + kc0;
    const float* Ag1 = A  + (size_t)(bm + row0 + 64) * FIN + kc0;
    const float* Bg0 = Bt + (size_t)(bn + row0)      * FIN + kc0;
    const float* Bg1 = Bt + (size_t)(bn + row0 + 64) * FIN + kc0;

    uint32_t sbase = smem_u32(sm);
    uint32_t dA0 = sbase + (uint32_t)(row0 * TSTRIDE + kc0) * 4;
    uint32_t dA1 = dA0 + (uint32_t)(64 * TSTRIDE) * 4;
    uint32_t dB0 = dA0 + (uint32_t)(128 * TSTRIDE) * 4;
    uint32_t dB1 = dB0 + (uint32_t)(64 * TSTRIDE) * 4;
    const uint32_t stageB = STAGE_FLOATS * 4;

    float acc[4][4][4];
#pragma unroll
    for (int i = 0; i < 4; i++)
#pragma unroll
        for (int j = 0; j < 4; j++)
#pragma unroll
            for (int q = 0; q < 4; q++) acc[i][j][q] = 0.0f;

    const int NK = FIN / 16;  // 32 stages

    // prologue: stages 0..2
#pragma unroll
    for (int s = 0; s < GSTAGES - 1; s++) {
        int k0 = s * 16;
        uint32_t so = s * stageB;
        cp_async16(dA0 + so, Ag0 + k0);
        cp_async16(dA1 + so, Ag1 + k0);
        cp_async16(dB0 + so, Bg0 + k0);
        cp_async16(dB1 + so, Bg1 + k0);
        CP_COMMIT();
    }
    CP_WAIT(GSTAGES - 2);  // stage 0 ready

    for (int i = 0; i < NK; i++) {
        __syncthreads();  // buf (i-1) fully consumed by all warps; buf i ready

        // issue loads for stage i+3 into buffer (i+3)&3
        if (i + GSTAGES - 1 < NK) {
            int k0 = (i + GSTAGES - 1) * 16;
            uint32_t so = ((i + GSTAGES - 1) & (GSTAGES - 1)) * stageB;
            cp_async16(dA0 + so, Ag0 + k0);
            cp_async16(dA1 + so, Ag1 + k0);
            cp_async16(dB0 + so, Bg0 + k0);
            cp_async16(dB1 + so, Bg1 + k0);
        }
        CP_COMMIT();  // empty groups at tail keep wait accounting aligned

        // compute stage i
        const float* As = sm + (i & (GSTAGES - 1)) * STAGE_FLOATS;
        const float* Bs = As + 128 * TSTRIDE;
#pragma unroll
        for (int kk = 0; kk < 2; kk++) {
            int k = kk * 8;
            uint32_t a[4][4];
#pragma unroll
            for (int mt = 0; mt < 4; mt++) {
                int mrow = wm * 64 + mt * 16 + g;
                a[mt][0] = __float_as_uint(As[mrow * TSTRIDE + k + t]);
                a[mt][1] = __float_as_uint(As[(mrow + 8) * TSTRIDE + k + t]);
                a[mt][2] = __float_as_uint(As[mrow * TSTRIDE + k + t + 4]);
                a[mt][3] = __float_as_uint(As[(mrow + 8) * TSTRIDE + k + t + 4]);
            }
            uint32_t b[4][2];
#pragma unroll
            for (int nt = 0; nt < 4; nt++) {
                int nrow = wn * 32 + nt * 8 + g;
                b[nt][0] = __float_as_uint(Bs[nrow * TSTRIDE + k + t]);
                b[nt][1] = __float_as_uint(Bs[nrow * TSTRIDE + k + t + 4]);
            }
#pragma unroll
            for (int mt = 0; mt < 4; mt++)
#pragma unroll
                for (int nt = 0; nt < 4; nt++)
                    mma_tf32(acc[mt][nt][0], acc[mt][nt][1], acc[mt][nt][2], acc[mt][nt][3],
                             a[mt][0], a[mt][1], a[mt][2], a[mt][3],
                             b[nt][0], b[nt][1]);
        }

        CP_WAIT(GSTAGES - 2);  // stage i+1 arrived
    }

    // ---- epilogue: lrelu + store ----
#pragma unroll
    for (int mt = 0; mt < 4; mt++) {
        int mrow = bm + wm * 64 + mt * 16 + g;
#pragma unroll
        for (int nt = 0; nt < 4; nt++) {
            int ncol = bn + wn * 32 + nt * 8 + t * 2;
            float2 lo, hi;
            lo.x = lrelu(acc[mt][nt][0]);
            lo.y = lrelu(acc[mt][nt][1]);
            hi.x = lrelu(acc[mt][nt][2]);
            hi.y = lrelu(acc[mt][nt][3]);
            *reinterpret_cast<float2*>(C + (size_t)mrow * FOUT + ncol)       = lo;
            *reinterpret_cast<float2*>(C + (size_t)(mrow + 8) * FOUT + ncol) = hi;
        }
    }
}

// ---------------- kernel 3: GAT softmax epilogue (9 warps, 1 dot per warp) ----------------
__global__ void gat_epilogue_kernel(const float* __restrict__ srcz,
                                    const float* __restrict__ hz,
                                    const float* __restrict__ a_attn,
                                    float*       __restrict__ msg)
{
    int n   = blockIdx.x;
    int tid = threadIdx.x;  // 288 = 9 warps
    int warp = tid >> 5, lane = tid & 31;

    __shared__ float zs[RR][FOUT];
    __shared__ float hzs[FOUT];
    __shared__ float scoresm[9];
    __shared__ float alpha[RR];

    const float4* zp4 = reinterpret_cast<const float4*>(srcz + (size_t)n * RR * FOUT);
    float4* zs4 = reinterpret_cast<float4*>(&zs[0][0]);
    for (int i = tid; i < RR * FOUT / 4; i += 288) zs4[i] = zp4[i];
    const float4* hp4 = reinterpret_cast<const float4*>(hz + (size_t)n * FOUT);
    float4* hzs4 = reinterpret_cast<float4*>(hzs);
    for (int i = tid; i < FOUT / 4; i += 288) hzs4[i] = hp4[i];
    __syncthreads();

    // warp w (0..7): dot(zs[w], a[:512]); warp 8: dot(hzs, a[512:])
    {
        const float4* src4 = (warp < 8) ? reinterpret_cast<const float4*>(&zs[warp][0])
                                        : reinterpret_cast<const float4*>(hzs);
        const float4* a4 = reinterpret_cast<const float4*>(a_attn + (warp < 8 ? 0 : FOUT));
        float s = 0.0f;
#pragma unroll
        for (int c = 0; c < 4; c++) {
            float4 z4 = src4[lane + c * 32];
            float4 av = a4[lane + c * 32];
            s += z4.x * av.x + z4.y * av.y + z4.z * av.z + z4.w * av.w;
        }
#pragma unroll
        for (int off = 16; off; off >>= 1)
            s += __shfl_down_sync(0xffffffffu, s, off);
        if (lane == 0) scoresm[warp] = s;
    }
    __syncthreads();

    if (tid == 0) {
        float sh = scoresm[8];
        float sc[RR], mx = -3.402823466e38f;
#pragma unroll
        for (int r = 0; r < RR; r++) {
            sc[r] = lrelu(scoresm[r] + sh);
            mx = fmaxf(mx, sc[r]);
        }
        float sum = 0.0f;
#pragma unroll
        for (int r = 0; r < RR; r++) {
            float e = expf(sc[r] - mx);
            alpha[r] = e;
            sum += e;
        }
        float inv = 1.0f / sum;
#pragma unroll
        for (int r = 0; r < RR; r++) alpha[r] *= inv;
    }
    __syncthreads();

    float al[RR];
#pragma unroll
    for (int r = 0; r < RR; r++) al[r] = alpha[r];

    for (int f = tid; f < FOUT; f += 288) {
        float acc = RESIDUAL * hzs[f];
#pragma unroll
        for (int r = 0; r < RR; r++) acc += al[r] * zs[r][f];
        msg[(size_t)n * FOUT + f] = acc;
    }
}

// ---------------- kernel 4: multi-attention + BatchNorm ----------------
__global__ void final_kernel(const float* __restrict__ Wp1,
                             const float* __restrict__ bp1,
                             const float* __restrict__ Wp2,
                             const float* __restrict__ bp2,
                             const float* __restrict__ gamma,
                             const float* __restrict__ betaBN,
                             const float* __restrict__ mean,
                             const float* __restrict__ var,
                             float*       __restrict__ out)
{
    int n   = blockIdx.x;
    int tid = threadIdx.x;  // 128

    __shared__ float z[2][FOUT];
    __shared__ float wred[4];
    __shared__ float betasm[2];

    for (int f = tid; f < FOUT; f += 128) {
        z[0][f] = g_msg[(size_t)n * FOUT + f];
        z[1][f] = g_msg[(size_t)NN * FOUT + (size_t)n * FOUT + f];
    }
    __syncthreads();

    int i  = tid >> 6;
    int hd = tid & 63;
    float acc = 0.0f;
#pragma unroll 8
    for (int k = 0; k < FOUT; k++) acc += z[i][k] * Wp1[k * HIDD + hd];
    float t  = tanhf(acc + bp1[hd]);
    float pw = t * Wp2[hd];

#pragma unroll
    for (int off = 16; off; off >>= 1)
        pw += __shfl_down_sync(0xffffffffu, pw, off);
    if ((tid & 31) == 0) wred[tid >> 5] = pw;
    __syncthreads();
    if (tid == 0) {
        float w0 = tanhf(wred[0] + wred[1] + bp2[0]);
        float w1 = tanhf(wred[2] + wred[3] + bp2[0]);
        float m  = fmaxf(w0, w1);
        float e0 = expf(w0 - m), e1 = expf(w1 - m);
        float inv = 1.0f / (e0 + e1);
        betasm[0] = e0 * inv;
        betasm[1] = e1 * inv;
    }
    __syncthreads();

    float b0 = betasm[0], b1 = betasm[1];
    for (int f = tid; f < FOUT; f += 128) {
        float v = b0 * z[0][f] + b1 * z[1][f];
        out[(size_t)n * FOUT + f] =
            (v - mean[f]) * rsqrtf(var[f] + BN_EPS) * gamma[f] + betaBN[f];
    }
}

// ---------------- launch ----------------
extern "C" void kernel_launch(void* const* d_in, const int* in_sizes, int n_in,
                              void* d_out, int out_size)
{
    const float* src_h     = (const float*)d_in[0];
    const float* src_h_img = (const float*)d_in[1];
    const int*   rel       = (const int*)  d_in[2];
    const float* h         = (const float*)d_in[3];
    const float* h_img     = (const float*)d_in[4];
    const float* W0        = (const float*)d_in[5];
    const float* a0        = (const float*)d_in[6];
    const float* W1        = (const float*)d_in[7];
    const float* a1        = (const float*)d_in[8];
    const float* Wp1       = (const float*)d_in[9];
    const float* bp1       = (const float*)d_in[10];
    const float* Wp2       = (const float*)d_in[11];
    const float* bp2       = (const float*)d_in[12];
    const float* gamma     = (const float*)d_in[13];
    const float* betaBN    = (const float*)d_in[14];
    const float* mean      = (const float*)d_in[15];
    const float* var       = (const float*)d_in[16];
    float* out = (float*)d_out;

    float *att, *srcz, *hz, *msg, *wt, *hconv;
    cudaGetSymbolAddress((void**)&att,   g_att);
    cudaGetSymbolAddress((void**)&srcz,  g_srcz);
    cudaGetSymbolAddress((void**)&hz,    g_hz);
    cudaGetSymbolAddress((void**)&msg,   g_msg);
    cudaGetSymbolAddress((void**)&wt,    g_wt);
    cudaGetSymbolAddress((void**)&hconv, g_hconv);

    static bool attr_set = false;
    if (!attr_set) {
        cudaFuncSetAttribute(gemm_tc_kernel,
                             cudaFuncAttributeMaxDynamicSharedMemorySize, GEMM_SMEM);
        attr_set = true;
    }

    const float* srcs[2] = {src_h, src_h_img};
    const float* hs[2]   = {h, h_img};
    const float* Ws[2]   = {W0, W1};
    const float* as[2]   = {a0, a1};

    for (int pass = 0; pass < 2; pass++) {
        transposeW_kernel<<<dim3(16, 16), dim3(32, 32)>>>(Ws[pass], wt);
        convert_kernel<<<(NN * FIN / 4 + 255) / 256, 256>>>(hs[pass], hconv, NN * FIN / 4);
        maxpool_kernel<<<NN, 128>>>(srcs[pass], rel, att);
        gemm_tc_kernel<<<dim3(FOUT / 128, (NN * RR) / 128), 256, GEMM_SMEM>>>(att, wt, srcz);
        gemm_tc_kernel<<<dim3(FOUT / 128, NN / 128), 256, GEMM_SMEM>>>(hconv, wt, hz);
        gat_epilogue_kernel<<<NN, 288>>>(srcz, hz, as[pass],
                                         msg + (size_t)pass * NN * FOUT);
    }
    final_kernel<<<NN, 128>>>(Wp1, bp1, Wp2, bp2, gamma, betaBN, mean, var, out);
}

// round 5
// speedup vs baseline: 2.8176x; 1.1100x over previous
#include <cuda_runtime.h>
#include <math.h>
#include <cstdint>

#define NN   16384
#define DD   16
#define FIN  512
#define FOUT 512
#define RR   8
#define HIDD 64
#define BN_EPS 1e-5f
#define RESIDUAL 0.12f

// ---------------- scratch (device globals: allocation-free) ----------------
__device__ float g_att  [(size_t)NN * RR * FIN];    // 268 MB (tf32-rounded)
__device__ float g_srcz [(size_t)NN * RR * FOUT];   // 268 MB
__device__ float g_hz   [(size_t)NN * FOUT];        // 33 MB
__device__ float g_msg  [2ull * NN * FOUT];         // 67 MB
__device__ float g_wt   [(size_t)FIN * FOUT];       // 1 MB (W^T, tf32-rounded)
__device__ float g_hconv[(size_t)NN * FIN];         // 33 MB (h, tf32-rounded)

__device__ __forceinline__ float lrelu(float x) { return x >= 0.0f ? x : 0.2f * x; }

__device__ __forceinline__ float to_tf32(float x) {
    float r;
    asm("cvt.rn.tf32.f32 %0, %1;" : "=f"(r) : "f"(x));
    return r;
}

__device__ __forceinline__ uint32_t smem_u32(const void* p) {
    uint32_t a;
    asm("{ .reg .u64 t; cvta.to.shared.u64 t, %1; cvt.u32.u64 %0, t; }" : "=r"(a) : "l"(p));
    return a;
}
__device__ __forceinline__ void cp_async16(uint32_t dst, const void* src) {
    asm volatile("cp.async.cg.shared.global [%0], [%1], 16;" :: "r"(dst), "l"(src));
}
#define CP_COMMIT() asm volatile("cp.async.commit_group;" ::: "memory")
#define CP_WAIT(n)  asm volatile("cp.async.wait_group %0;" :: "n"(n) : "memory")

__device__ __forceinline__ void ldsm_x4(uint32_t* r, uint32_t addr) {
    asm volatile("ldmatrix.sync.aligned.m8n8.x4.shared.b16 {%0,%1,%2,%3}, [%4];"
        : "=r"(r[0]), "=r"(r[1]), "=r"(r[2]), "=r"(r[3]) : "r"(addr));
}

__device__ __forceinline__ void mma_tf32(float& c0, float& c1, float& c2, float& c3,
                                         uint32_t a0, uint32_t a1, uint32_t a2, uint32_t a3,
                                         uint32_t b0, uint32_t b1) {
    asm volatile(
        "mma.sync.aligned.m16n8k8.row.col.f32.tf32.tf32.f32 "
        "{%0,%1,%2,%3}, {%4,%5,%6,%7}, {%8,%9}, {%0,%1,%2,%3};"
        : "+f"(c0), "+f"(c1), "+f"(c2), "+f"(c3)
        : "r"(a0), "r"(a1), "r"(a2), "r"(a3), "r"(b0), "r"(b1));
}

// ---------------- kernel 0a: transpose W [K,N] -> WT [N,K], tf32 round ----------------
__global__ void transposeW_kernel(const float* __restrict__ W, float* __restrict__ WT)
{
    __shared__ float t[32][33];
    int bx = blockIdx.x * 32, by = blockIdx.y * 32;
    t[threadIdx.y][threadIdx.x] = W[(by + threadIdx.y) * FOUT + bx + threadIdx.x];
    __syncthreads();
    WT[(bx + threadIdx.y) * FIN + by + threadIdx.x] = to_tf32(t[threadIdx.x][threadIdx.y]);
}

// ---------------- kernel 0b: round h to tf32 ----------------
__global__ void convert_kernel(const float* __restrict__ in, float* __restrict__ out, int n4)
{
    int i = blockIdx.x * blockDim.x + threadIdx.x;
    if (i < n4) {
        float4 v = reinterpret_cast<const float4*>(in)[i];
        v.x = to_tf32(v.x); v.y = to_tf32(v.y);
        v.z = to_tf32(v.z); v.w = to_tf32(v.w);
        reinterpret_cast<float4*>(out)[i] = v;
    }
}

// ---------------- kernel 1: relation maxpool (tf32-rounded output) ----------------
__global__ void maxpool_kernel(const float* __restrict__ src,
                               const int*   __restrict__ rel,
                               float*       __restrict__ att)
{
    int n   = blockIdx.x;
    int tid = threadIdx.x;  // 128

    __shared__ int rl[DD];
    __shared__ int cnt[RR];
    if (tid < RR) cnt[tid] = 0;
    __syncthreads();
    if (tid < DD) {
        int r = rel[n * DD + tid];
        rl[tid] = r;
        atomicAdd(&cnt[r], 1);
    }
    __syncthreads();

    const float4* sp = reinterpret_cast<const float4*>(src + (size_t)n * DD * FIN);
    const float NEG = -3.402823466e38f;

    float4 mx[RR];
#pragma unroll
    for (int r = 0; r < RR; r++) mx[r] = make_float4(NEG, NEG, NEG, NEG);

#pragma unroll
    for (int d = 0; d < DD; d++) {
        float4 v = sp[d * (FIN / 4) + tid];
        int rd = rl[d];
#pragma unroll
        for (int r = 0; r < RR; r++) {
            bool m = (rd == r);
            mx[r].x = m ? fmaxf(mx[r].x, v.x) : mx[r].x;
            mx[r].y = m ? fmaxf(mx[r].y, v.y) : mx[r].y;
            mx[r].z = m ? fmaxf(mx[r].z, v.z) : mx[r].z;
            mx[r].w = m ? fmaxf(mx[r].w, v.w) : mx[r].w;
        }
    }

    float4* ap = reinterpret_cast<float4*>(att + (size_t)n * RR * FIN);
#pragma unroll
    for (int r = 0; r < RR; r++) {
        float4 o = mx[r];
        if (cnt[r] != DD) {
            o.x = fmaxf(o.x, 0.0f);
            o.y = fmaxf(o.y, 0.0f);
            o.z = fmaxf(o.z, 0.0f);
            o.w = fmaxf(o.w, 0.0f);
        }
        o.x = to_tf32(o.x); o.y = to_tf32(o.y);
        o.z = to_tf32(o.z); o.w = to_tf32(o.w);
        ap[r * (FIN / 4) + tid] = o;
    }
}

// ---------------- kernel 2: mma.sync tf32 GEMM with ldmatrix fragments ----------------
// Fused: blocks y<1024 compute srcz = lrelu(att @ WT^T); y>=1024 compute hz from hconv.
// 4-stage cp.async ring, one __syncthreads per BK=16 stage.
// BM=128, BN=128, BK=16. 256 threads, 8 warps (2M x 4N), warp tile 64x32.
#define TSTRIDE 20                        // smem row stride (floats)
#define STAGE_FLOATS (2 * 128 * TSTRIDE)  // A tile + B tile per stage
#define GSTAGES 4
#define GEMM_SMEM (GSTAGES * STAGE_FLOATS * 4)  // 81920 bytes
#define MBBIG (NN * RR / 128)             // 1024 row-blocks for the big GEMM

__global__ void __launch_bounds__(256, 2)
gemm_tc_kernel(const float* __restrict__ Abig,
               const float* __restrict__ Asmall,
               const float* __restrict__ Bt,
               float*       __restrict__ Cbig,
               float*       __restrict__ Csmall)
{
    extern __shared__ float sm[];
    int tid  = threadIdx.x;
    int wid  = tid >> 5;
    int lane = tid & 31;
    int wm   = wid & 1;
    int wn   = wid >> 1;
    int g    = lane >> 2;
    int t    = lane & 3;
    int q    = lane >> 3;   // ldmatrix quadrant 0..3
    int lr   = lane & 7;

    int mb = blockIdx.y;
    const float* A;
    float* C;
    int bm;
    if (mb < MBBIG) { A = Abig;   C = Cbig;   bm = mb * 128; }
    else            { A = Asmall; C = Csmall; bm = (mb - MBBIG) * 128; }
    int bn = blockIdx.x * 128;

    int row0 = tid >> 2;              // 0..63
    int kc0  = (tid & 3) * 4;         // 0,4,8,12
    const float* Ag0 = A  + (size_t)(bm + row0)      * FIN + kc0;
    const float* Ag1 = A  + (size_t)(bm + row0 + 64) * FIN + kc0;
    const float* Bg0 = Bt + (size_t)(bn + row0)      * FIN + kc0;
    const float* Bg1 = Bt + (size_t)(bn + row0 + 64) * FIN + kc0;

    uint32_t sbase = smem_u32(sm);
    uint32_t dA0 = sbase + (uint32_t)(row0 * TSTRIDE + kc0) * 4;
    uint32_t dA1 = dA0 + (uint32_t)(64 * TSTRIDE) * 4;
    uint32_t dB0 = dA0 + (uint32_t)(128 * TSTRIDE) * 4;
    uint32_t dB1 = dB0 + (uint32_t)(64 * TSTRIDE) * 4;
    const uint32_t stageB = STAGE_FLOATS * 4;

    // ldmatrix per-lane source offsets (bytes) within a stage
    // A x4: quadrants (q&1 -> +8 rows, q>>1 -> +4 cols) of the 16x8 tile
    uint32_t laneAoff = (uint32_t)((wm * 64 + (q & 1) * 8 + lr) * TSTRIDE + (q >> 1) * 4) * 4;
    // B x4: m0,m1 = ntile0 cols k,k+4 ; m2,m3 = ntile1 (rows +8)
    uint32_t laneBoff = (uint32_t)((128 + wn * 32 + (q >> 1) * 8 + lr) * TSTRIDE + (q & 1) * 4) * 4;

    float acc[4][4][4];
#pragma unroll
    for (int i = 0; i < 4; i++)
#pragma unroll
        for (int j = 0; j < 4; j++)
#pragma unroll
            for (int x = 0; x < 4; x++) acc[i][j][x] = 0.0f;

    const int NK = FIN / 16;  // 32 stages

    // prologue: stages 0..2
#pragma unroll
    for (int s = 0; s < GSTAGES - 1; s++) {
        int k0 = s * 16;
        uint32_t so = s * stageB;
        cp_async16(dA0 + so, Ag0 + k0);
        cp_async16(dA1 + so, Ag1 + k0);
        cp_async16(dB0 + so, Bg0 + k0);
        cp_async16(dB1 + so, Bg1 + k0);
        CP_COMMIT();
    }
    CP_WAIT(GSTAGES - 2);  // stage 0 ready

    for (int i = 0; i < NK; i++) {
        __syncthreads();

        if (i + GSTAGES - 1 < NK) {
            int k0 = (i + GSTAGES - 1) * 16;
            uint32_t so = ((i + GSTAGES - 1) & (GSTAGES - 1)) * stageB;
            cp_async16(dA0 + so, Ag0 + k0);
            cp_async16(dA1 + so, Ag1 + k0);
            cp_async16(dB0 + so, Bg0 + k0);
            cp_async16(dB1 + so, Bg1 + k0);
        }
        CP_COMMIT();

        uint32_t sa = sbase + (i & (GSTAGES - 1)) * stageB;
        uint32_t aA = sa + laneAoff;
        uint32_t aB = sa + laneBoff;
#pragma unroll
        for (int kk = 0; kk < 2; kk++) {
            uint32_t a[4][4];
            uint32_t b[2][4];
#pragma unroll
            for (int mt = 0; mt < 4; mt++)
                ldsm_x4(a[mt], aA + (uint32_t)(mt * 16 * TSTRIDE + kk * 8) * 4);
#pragma unroll
            for (int n2 = 0; n2 < 2; n2++)
                ldsm_x4(b[n2], aB + (uint32_t)(n2 * 16 * TSTRIDE + kk * 8) * 4);
#pragma unroll
            for (int mt = 0; mt < 4; mt++)
#pragma unroll
                for (int nt = 0; nt < 4; nt++)
                    mma_tf32(acc[mt][nt][0], acc[mt][nt][1], acc[mt][nt][2], acc[mt][nt][3],
                             a[mt][0], a[mt][1], a[mt][2], a[mt][3],
                             b[nt >> 1][(nt & 1) * 2], b[nt >> 1][(nt & 1) * 2 + 1]);
        }

        CP_WAIT(GSTAGES - 2);
    }

    // ---- epilogue: lrelu + store ----
#pragma unroll
    for (int mt = 0; mt < 4; mt++) {
        int mrow = bm + wm * 64 + mt * 16 + g;
#pragma unroll
        for (int nt = 0; nt < 4; nt++) {
            int ncol = bn + wn * 32 + nt * 8 + t * 2;
            float2 lo, hi;
            lo.x = lrelu(acc[mt][nt][0]);
            lo.y = lrelu(acc[mt][nt][1]);
            hi.x = lrelu(acc[mt][nt][2]);
            hi.y = lrelu(acc[mt][nt][3]);
            *reinterpret_cast<float2*>(C + (size_t)mrow * FOUT + ncol)       = lo;
            *reinterpret_cast<float2*>(C + (size_t)(mrow + 8) * FOUT + ncol) = hi;
        }
    }
}

// ---------------- kernel 3: GAT softmax epilogue (9 warps, 1 dot per warp) ----------------
__global__ void gat_epilogue_kernel(const float* __restrict__ srcz,
                                    const float* __restrict__ hz,
                                    const float* __restrict__ a_attn,
                                    float*       __restrict__ msg)
{
    int n   = blockIdx.x;
    int tid = threadIdx.x;  // 288 = 9 warps
    int warp = tid >> 5, lane = tid & 31;

    __shared__ float zs[RR][FOUT];
    __shared__ float hzs[FOUT];
    __shared__ float scoresm[9];
    __shared__ float alpha[RR];

    const float4* zp4 = reinterpret_cast<const float4*>(srcz + (size_t)n * RR * FOUT);
    float4* zs4 = reinterpret_cast<float4*>(&zs[0][0]);
    for (int i = tid; i < RR * FOUT / 4; i += 288) zs4[i] = zp4[i];
    const float4* hp4 = reinterpret_cast<const float4*>(hz + (size_t)n * FOUT);
    float4* hzs4 = reinterpret_cast<float4*>(hzs);
    for (int i = tid; i < FOUT / 4; i += 288) hzs4[i] = hp4[i];
    __syncthreads();

    {
        const float4* src4 = (warp < 8) ? reinterpret_cast<const float4*>(&zs[warp][0])
                                        : reinterpret_cast<const float4*>(hzs);
        const float4* a4 = reinterpret_cast<const float4*>(a_attn + (warp < 8 ? 0 : FOUT));
        float s = 0.0f;
#pragma unroll
        for (int c = 0; c < 4; c++) {
            float4 z4 = src4[lane + c * 32];
            float4 av = a4[lane + c * 32];
            s += z4.x * av.x + z4.y * av.y + z4.z * av.z + z4.w * av.w;
        }
#pragma unroll
        for (int off = 16; off; off >>= 1)
            s += __shfl_down_sync(0xffffffffu, s, off);
        if (lane == 0) scoresm[warp] = s;
    }
    __syncthreads();

    if (tid == 0) {
        float sh = scoresm[8];
        float sc[RR], mx = -3.402823466e38f;
#pragma unroll
        for (int r = 0; r < RR; r++) {
            sc[r] = lrelu(scoresm[r] + sh);
            mx = fmaxf(mx, sc[r]);
        }
        float sum = 0.0f;
#pragma unroll
        for (int r = 0; r < RR; r++) {
            float e = expf(sc[r] - mx);
            alpha[r] = e;
            sum += e;
        }
        float inv = 1.0f / sum;
#pragma unroll
        for (int r = 0; r < RR; r++) alpha[r] *= inv;
    }
    __syncthreads();

    float al[RR];
#pragma unroll
    for (int r = 0; r < RR; r++) al[r] = alpha[r];

    for (int f = tid; f < FOUT; f += 288) {
        float acc = RESIDUAL * hzs[f];
#pragma unroll
        for (int r = 0; r < RR; r++) acc += al[r] * zs[r][f];
        msg[(size_t)n * FOUT + f] = acc;
    }
}

// ---------------- kernel 4: multi-attention + BatchNorm ----------------
__global__ void final_kernel(const float* __restrict__ Wp1,
                             const float* __restrict__ bp1,
                             const float* __restrict__ Wp2,
                             const float* __restrict__ bp2,
                             const float* __restrict__ gamma,
                             const float* __restrict__ betaBN,
                             const float* __restrict__ mean,
                             const float* __restrict__ var,
                             float*       __restrict__ out)
{
    int n   = blockIdx.x;
    int tid = threadIdx.x;  // 128

    __shared__ float z[2][FOUT];
    __shared__ float wred[4];
    __shared__ float betasm[2];

    for (int f = tid; f < FOUT; f += 128) {
        z[0][f] = g_msg[(size_t)n * FOUT + f];
        z[1][f] = g_msg[(size_t)NN * FOUT + (size_t)n * FOUT + f];
    }
    __syncthreads();

    int i  = tid >> 6;
    int hd = tid & 63;
    float acc = 0.0f;
#pragma unroll 8
    for (int k = 0; k < FOUT; k++) acc += z[i][k] * Wp1[k * HIDD + hd];
    float t  = tanhf(acc + bp1[hd]);
    float pw = t * Wp2[hd];

#pragma unroll
    for (int off = 16; off; off >>= 1)
        pw += __shfl_down_sync(0xffffffffu, pw, off);
    if ((tid & 31) == 0) wred[tid >> 5] = pw;
    __syncthreads();
    if (tid == 0) {
        float w0 = tanhf(wred[0] + wred[1] + bp2[0]);
        float w1 = tanhf(wred[2] + wred[3] + bp2[0]);
        float m  = fmaxf(w0, w1);
        float e0 = expf(w0 - m), e1 = expf(w1 - m);
        float inv = 1.0f / (e0 + e1);
        betasm[0] = e0 * inv;
        betasm[1] = e1 * inv;
    }
    __syncthreads();

    float b0 = betasm[0], b1 = betasm[1];
    for (int f = tid; f < FOUT; f += 128) {
        float v = b0 * z[0][f] + b1 * z[1][f];
        out[(size_t)n * FOUT + f] =
            (v - mean[f]) * rsqrtf(var[f] + BN_EPS) * gamma[f] + betaBN[f];
    }
}

// ---------------- launch ----------------
extern "C" void kernel_launch(void* const* d_in, const int* in_sizes, int n_in,
                              void* d_out, int out_size)
{
    const float* src_h     = (const float*)d_in[0];
    const float* src_h_img = (const float*)d_in[1];
    const int*   rel       = (const int*)  d_in[2];
    const float* h         = (const float*)d_in[3];
    const float* h_img     = (const float*)d_in[4];
    const float* W0        = (const float*)d_in[5];
    const float* a0        = (const float*)d_in[6];
    const float* W1        = (const float*)d_in[7];
    const float* a1        = (const float*)d_in[8];
    const float* Wp1       = (const float*)d_in[9];
    const float* bp1       = (const float*)d_in[10];
    const float* Wp2       = (const float*)d_in[11];
    const float* bp2       = (const float*)d_in[12];
    const float* gamma     = (const float*)d_in[13];
    const float* betaBN    = (const float*)d_in[14];
    const float* mean      = (const float*)d_in[15];
    const float* var       = (const float*)d_in[16];
    float* out = (float*)d_out;

    float *att, *srcz, *hz, *msg, *wt, *hconv;
    cudaGetSymbolAddress((void**)&att,   g_att);
    cudaGetSymbolAddress((void**)&srcz,  g_srcz);
    cudaGetSymbolAddress((void**)&hz,    g_hz);
    cudaGetSymbolAddress((void**)&msg,   g_msg);
    cudaGetSymbolAddress((void**)&wt,    g_wt);
    cudaGetSymbolAddress((void**)&hconv, g_hconv);

    static bool attr_set = false;
    if (!attr_set) {
        cudaFuncSetAttribute(gemm_tc_kernel,
                             cudaFuncAttributeMaxDynamicSharedMemorySize, GEMM_SMEM);
        attr_set = true;
    }

    const float* srcs[2] = {src_h, src_h_img};
    const float* hs[2]   = {h, h_img};
    const float* Ws[2]   = {W0, W1};
    const float* as[2]   = {a0, a1};

    for (int pass = 0; pass < 2; pass++) {
        transposeW_kernel<<<dim3(16, 16), dim3(32, 32)>>>(Ws[pass], wt);
        convert_kernel<<<(NN * FIN / 4 + 255) / 256, 256>>>(hs[pass], hconv, NN * FIN / 4);
        maxpool_kernel<<<NN, 128>>>(srcs[pass], rel, att);
        gemm_tc_kernel<<<dim3(FOUT / 128, MBBIG + NN / 128), 256, GEMM_SMEM>>>(
            att, hconv, wt, srcz, hz);
        gat_epilogue_kernel<<<NN, 288>>>(srcz, hz, as[pass],
                                         msg + (size_t)pass * NN * FOUT);
    }
    final_kernel<<<NN, 128>>>(Wp1, bp1, Wp2, bp2, gamma, betaBN, mean, var, out);
}